// round 2
// baseline (speedup 1.0000x reference)
#include <cuda_runtime.h>

// Problem constants
#define BATCH 256
#define HWDIM 128
#define OCN   16
#define PO    63            // pooled spatial dim
#define FTOT  63504         // 16*63*63
#define NHID  256
#define FANIN 512
#define NOUT  10
#define SPLIT 57344         // feats staged in smem for the gather (224 KB)

// Scratch (static device arrays per allocation rules)
__device__ float g_feats[(size_t)BATCH * FTOT];   // pooled features, fp32
__device__ float g_hidden[BATCH * NHID];
__device__ int2  g_pairs[NHID * FANIN];           // packed (idx, w-bits)

typedef unsigned long long u64;

// ---- f32x2 packed-FMA helpers (FFMA2 path, only reachable via PTX) ----
__device__ __forceinline__ u64 pk2(float lo, float hi) {
    u64 r;
    asm("mov.b64 %0, {%1, %2};"
        : "=l"(r) : "r"(__float_as_uint(lo)), "r"(__float_as_uint(hi)));
    return r;
}
__device__ __forceinline__ u64 ffma2(u64 a, u64 b, u64 c) {
    u64 d;
    asm("fma.rn.f32x2 %0, %1, %2, %3;"
        : "=l"(d) : "l"(a), "l"(b), "l"(c));
    return d;
}
__device__ __forceinline__ void upk2(u64 v, float& lo, float& hi) {
    unsigned int a, b;
    asm("mov.b64 {%0, %1}, %2;" : "=r"(a), "=r"(b) : "l"(v));
    lo = __uint_as_float(a);
    hi = __uint_as_float(b);
}

// ============================================================
// Kernel A: conv3x3 (VALID) + bias + relu + maxpool2x2 -> g_feats
// Tile: 21x21 pooled outputs (42x42 conv area, 44x44 input area), all 16 oc.
// Grid: (9 tiles, 256 batches), 256 threads.
// f32x2 packs the two pooled sub-columns (sx=0,1); weights pre-packed {w,w}.
// ============================================================
__global__ __launch_bounds__(256) void conv_pool_kernel(
    const float* __restrict__ in,
    const float* __restrict__ cw,
    const float* __restrict__ cb)
{
    __shared__ float s_in[3 * 44 * 44];
    __shared__ u64   s_wp[16 * 27];
    __shared__ float s_b[16];

    const int tile = blockIdx.x;       // 0..8
    const int b    = blockIdx.y;
    const int ty   = tile / 3, tx = tile % 3;
    const int tid  = threadIdx.x;

    // weights packed {w,w} for FFMA2; conv_w is [16][3][3][3] = 432 contiguous
    // (R1 bug: `if (tid < 432)` with 256 threads left oc>=9 weights garbage)
    for (int i = tid; i < 432; i += 256) {
        unsigned int u = __float_as_uint(cw[i]);
        s_wp[i] = ((u64)u << 32) | (u64)u;
    }
    if (tid < 16) s_b[tid] = cb[tid];

    // stage input tile 3 x 44 x 44
    const int iy0 = 42 * ty, ix0 = 42 * tx;
    for (int i = tid; i < 3 * 44 * 44; i += 256) {
        int c = i / (44 * 44);
        int r = (i % (44 * 44)) / 44;
        int x = i % 44;
        s_in[i] = in[(((size_t)b * 3 + c) * HWDIM + (iy0 + r)) * HWDIM + (ix0 + x)];
    }
    __syncthreads();

    for (int p = tid; p < 441; p += 256) {
        const int lpy = p / 21, lpx = p % 21;

        // 3ch x 4x4 input window covering the 2x2 conv pixels of this pooled output
        float win[3][4][4];
        #pragma unroll
        for (int c = 0; c < 3; c++) {
            #pragma unroll
            for (int yy = 0; yy < 4; yy++) {
                const float* rp = &s_in[c * 1936 + (2 * lpy + yy) * 44 + 2 * lpx];
                float2 v0 = *(const float2*)rp;         // 8B-aligned (2*lpx even)
                float2 v1 = *(const float2*)(rp + 2);
                win[c][yy][0] = v0.x; win[c][yy][1] = v0.y;
                win[c][yy][2] = v1.x; win[c][yy][3] = v1.y;
            }
        }

        #pragma unroll
        for (int g = 0; g < 2; g++) {          // two groups of 8 output channels
            u64 acc0[8], acc1[8];              // acc0: sy=0 (sx0,sx1); acc1: sy=1
            #pragma unroll
            for (int o = 0; o < 8; o++) { acc0[o] = 0ull; acc1[o] = 0ull; }

            #pragma unroll
            for (int c = 0; c < 3; c++) {
                #pragma unroll
                for (int ky = 0; ky < 3; ky++) {
                    #pragma unroll
                    for (int kx = 0; kx < 3; kx++) {
                        u64 a0 = pk2(win[c][ky    ][kx], win[c][ky    ][kx + 1]);
                        u64 a1 = pk2(win[c][ky + 1][kx], win[c][ky + 1][kx + 1]);
                        const int widx = c * 9 + ky * 3 + kx;
                        #pragma unroll
                        for (int o = 0; o < 8; o++) {
                            u64 wp = s_wp[(g * 8 + o) * 27 + widx];  // LDS.64 broadcast
                            acc0[o] = ffma2(a0, wp, acc0[o]);
                            acc1[o] = ffma2(a1, wp, acc1[o]);
                        }
                    }
                }
            }

            #pragma unroll
            for (int o = 0; o < 8; o++) {
                float c00, c01, c10, c11;
                upk2(acc0[o], c00, c01);
                upk2(acc1[o], c10, c11);
                float m  = fmaxf(fmaxf(c00, c01), fmaxf(c10, c11));
                int   oc = g * 8 + o;
                float v  = fmaxf(m + s_b[oc], 0.0f);   // max(relu(x+b)) == relu(max(x)+b)
                int py = ty * 21 + lpy, px = tx * 21 + lpx;
                g_feats[(size_t)b * FTOT + (oc * PO + py) * PO + px] = v;
            }
        }
    }
}

// ============================================================
// Prep: pack (idx, w) into int2 so the gather loop does 1 LDG.64 per term
// ============================================================
__global__ void pack_pairs_kernel(const int* __restrict__ idx,
                                  const float* __restrict__ w)
{
    int i = blockIdx.x * blockDim.x + threadIdx.x;
    if (i < NHID * FANIN) g_pairs[i] = make_int2(idx[i], __float_as_int(w[i]));
}

// ============================================================
// Kernel B: hidden = sigmoid(sum_k feats[b, idx[h,k]] * w[h,k] + b[h])
// One CTA per batch. First SPLIT feats staged in 224 KB smem (exact fp32);
// ~90% of random gathers become LDS, tail falls through to L2-resident gmem.
// ============================================================
__global__ __launch_bounds__(512) void hidden_kernel(const float* __restrict__ hb)
{
    extern __shared__ float sf[];
    const int b = blockIdx.x;
    const float* frow = g_feats + (size_t)b * FTOT;

    // stage fp32 feats (vectorized; SPLIT divisible by 4)
    {
        const float4* s4 = (const float4*)frow;
        float4* d4 = (float4*)sf;
        for (int i = threadIdx.x; i < SPLIT / 4; i += 512) d4[i] = s4[i];
    }
    __syncthreads();

    const int warp = threadIdx.x >> 5, lane = threadIdx.x & 31;

    for (int h = warp; h < NHID; h += 16) {
        float acc0 = 0.f, acc1 = 0.f;
        #pragma unroll
        for (int it = 0; it < 8; it++) {
            int  i0 = h * FANIN + it * 32 + lane;
            int2 p0 = g_pairs[i0];
            int2 p1 = g_pairs[i0 + 256];
            float f0 = (p0.x < SPLIT) ? sf[p0.x] : __ldg(&frow[p0.x]);
            float f1 = (p1.x < SPLIT) ? sf[p1.x] : __ldg(&frow[p1.x]);
            acc0 = fmaf(f0, __int_as_float(p0.y), acc0);
            acc1 = fmaf(f1, __int_as_float(p1.y), acc1);
        }
        float acc = acc0 + acc1;
        #pragma unroll
        for (int s = 16; s; s >>= 1) acc += __shfl_xor_sync(0xffffffffu, acc, s);
        if (lane == 0)
            g_hidden[b * NHID + h] = 1.f / (1.f + expf(-(acc + hb[h])));
    }
}

// ============================================================
// Kernel C: out = sigmoid(hidden @ out_w^T + out_b)   [256 x 10]
// One CTA per batch, one warp per output.
// ============================================================
__global__ __launch_bounds__(320) void out_kernel(
    const float* __restrict__ ow,
    const float* __restrict__ ob,
    float* __restrict__ out)
{
    const int b = blockIdx.x;
    const int warp = threadIdx.x >> 5, lane = threadIdx.x & 31;
    if (warp < NOUT) {
        float acc = 0.f;
        #pragma unroll
        for (int i = 0; i < NHID / 32; i++) {
            int j = i * 32 + lane;
            acc = fmaf(g_hidden[b * NHID + j], ow[warp * NHID + j], acc);
        }
        #pragma unroll
        for (int s = 16; s; s >>= 1) acc += __shfl_xor_sync(0xffffffffu, acc, s);
        if (lane == 0)
            out[b * NOUT + warp] = 1.f / (1.f + expf(-(acc + ob[warp])));
    }
}

// ============================================================
extern "C" void kernel_launch(void* const* d_in, const int* in_sizes, int n_in,
                              void* d_out, int out_size)
{
    const float* inputs = (const float*)d_in[0];
    const float* conv_w = (const float*)d_in[1];
    const float* conv_b = (const float*)d_in[2];
    const int*   hidx   = (const int*)d_in[3];
    const float* hw     = (const float*)d_in[4];
    const float* hb     = (const float*)d_in[5];
    const float* ow     = (const float*)d_in[6];
    const float* ob     = (const float*)d_in[7];

    // idempotent; executes immediately (not a stream op), safe under capture
    cudaFuncSetAttribute(hidden_kernel,
                         cudaFuncAttributeMaxDynamicSharedMemorySize, SPLIT * 4);

    pack_pairs_kernel<<<(NHID * FANIN + 255) / 256, 256>>>(hidx, hw);
    conv_pool_kernel<<<dim3(9, BATCH), 256>>>(inputs, conv_w, conv_b);
    hidden_kernel<<<BATCH, 512, SPLIT * 4>>>(hb);
    out_kernel<<<BATCH, 320>>>(ow, ob, (float*)d_out);
}

// round 3
// speedup vs baseline: 1.5011x; 1.5011x over previous
#include <cuda_runtime.h>

// Problem constants
#define BATCH 256
#define HWDIM 128
#define OCN   16
#define PO    63            // pooled spatial dim
#define FTOT  63504         // 16*63*63
#define NHID  256
#define FANIN 512
#define NOUT  10
#define SPLIT 57344         // feats staged in smem for the gather (224 KB)

// Scratch (static device arrays per allocation rules)
__device__ float g_feats[(size_t)BATCH * FTOT];   // pooled features, fp32
__device__ int2  g_pairs[NHID * FANIN];           // packed (idx, w-bits)

// ============================================================
// Kernel A: conv3x3 (VALID) + bias + relu + maxpool2x2 -> g_feats
// Plain fp32 FFMA (no f32x2 — R2 post-mortem: fma.rn.f32x2 ran ~15x slow).
// Tile: 21x21 pooled outputs (44x44 input halo), all 16 oc.
// Grid: (9 tiles, 256 batches), 224 threads (441 = 2 near-full passes).
// Weights transposed to s_w[widx][16] so each (pix,widx) needs 4 broadcast
// LDS.128; accumulators: 16 cur + 16 pooled floats -> ~50 regs, no spills.
// Also folds the (idx,w) pair-packing for the hidden kernel into the first
// 512 CTAs.
// ============================================================
__global__ __launch_bounds__(224) void conv_pool_kernel(
    const float* __restrict__ in,
    const float* __restrict__ cw,
    const float* __restrict__ cb,
    const int*   __restrict__ hidx,
    const float* __restrict__ hw)
{
    __shared__ float s_in[3 * 44 * 44];
    __shared__ float s_w[27][16];      // [c*9+ky*3+kx][oc], rows 64B -> LDS.128 ok
    __shared__ float s_b[16];

    const int tile = blockIdx.x;       // 0..8
    const int b    = blockIdx.y;
    const int ty   = tile / 3, tx = tile % 3;
    const int tid  = threadIdx.x;

    // ---- folded pack_pairs: linear CTA id < 512 packs 256 pairs each ----
    {
        const int bid = b * 9 + tile;
        if (bid < 512) {
            for (int i = tid; i < 256; i += 224) {
                int j = bid * 256 + i;
                g_pairs[j] = make_int2(hidx[j], __float_as_int(hw[j]));
            }
        }
    }

    // ---- stage weights (transposed) + bias ----
    for (int i = tid; i < 432; i += 224) {
        int oc = i / 27, widx = i % 27;       // conv_w is [16][27]
        s_w[widx][oc] = cw[i];
    }
    if (tid < 16) s_b[tid] = cb[tid];

    // ---- stage input tile 3 x 44 x 44 ----
    const int iy0 = 42 * ty, ix0 = 42 * tx;
    for (int i = tid; i < 3 * 44 * 44; i += 224) {
        int c = i / 1936;
        int r = (i % 1936) / 44;
        int x = i % 44;
        s_in[i] = in[(((size_t)b * 3 + c) * HWDIM + (iy0 + r)) * HWDIM + (ix0 + x)];
    }
    __syncthreads();

    for (int p = tid; p < 441; p += 224) {
        const int lpy = p / 21, lpx = p % 21;

        float pool[16];
        #pragma unroll
        for (int o = 0; o < 16; o++) pool[o] = -3.4e38f;

        #pragma unroll
        for (int sy = 0; sy < 2; sy++) {
            #pragma unroll
            for (int sx = 0; sx < 2; sx++) {
                float cur[16];
                #pragma unroll
                for (int o = 0; o < 16; o++) cur[o] = 0.0f;

                #pragma unroll
                for (int c = 0; c < 3; c++) {
                    #pragma unroll
                    for (int ky = 0; ky < 3; ky++) {
                        const float* rp =
                            &s_in[c * 1936 + (2 * lpy + sy + ky) * 44 + 2 * lpx + sx];
                        #pragma unroll
                        for (int kx = 0; kx < 3; kx++) {
                            float a = rp[kx];
                            const float4* w4p =
                                (const float4*)s_w[c * 9 + ky * 3 + kx];
                            #pragma unroll
                            for (int og = 0; og < 4; og++) {
                                float4 w = w4p[og];   // broadcast LDS.128
                                cur[og * 4 + 0] = fmaf(a, w.x, cur[og * 4 + 0]);
                                cur[og * 4 + 1] = fmaf(a, w.y, cur[og * 4 + 1]);
                                cur[og * 4 + 2] = fmaf(a, w.z, cur[og * 4 + 2]);
                                cur[og * 4 + 3] = fmaf(a, w.w, cur[og * 4 + 3]);
                            }
                        }
                    }
                }
                #pragma unroll
                for (int o = 0; o < 16; o++) pool[o] = fmaxf(pool[o], cur[o]);
            }
        }

        const int py = ty * 21 + lpy, px = tx * 21 + lpx;
        #pragma unroll
        for (int o = 0; o < 16; o++) {
            float v = fmaxf(pool[o] + s_b[o], 0.0f);  // max(relu) == relu(max)+b ok
            g_feats[(size_t)b * FTOT + (o * PO + py) * PO + px] = v;
        }
    }
}

// ============================================================
// Kernel B (fused): hidden = sigmoid(gather-dot + hb), then
// out = sigmoid(hidden @ out_w^T + ob). One CTA per batch.
// First SPLIT feats staged in 224 KB smem; ~90% of gathers become LDS,
// tail (6160 feats = 24.6 KB) stays L2/L1-resident via __ldg.
// ============================================================
__global__ __launch_bounds__(512) void hidden_out_kernel(
    const float* __restrict__ hb,
    const float* __restrict__ ow,
    const float* __restrict__ ob,
    float* __restrict__ out)
{
    extern __shared__ float sf[];      // SPLIT floats
    __shared__ float s_h[NHID];

    const int b = blockIdx.x;
    const float* frow = g_feats + (size_t)b * FTOT;

    // stage fp32 feats (vectorized; SPLIT divisible by 4)
    {
        const float4* s4 = (const float4*)frow;
        float4* d4 = (float4*)sf;
        for (int i = threadIdx.x; i < SPLIT / 4; i += 512) d4[i] = s4[i];
    }
    __syncthreads();

    const int warp = threadIdx.x >> 5, lane = threadIdx.x & 31;

    for (int h = warp; h < NHID; h += 16) {
        float acc0 = 0.f, acc1 = 0.f;
        #pragma unroll
        for (int it = 0; it < 8; it++) {
            int  i0 = h * FANIN + it * 32 + lane;
            int2 p0 = g_pairs[i0];
            int2 p1 = g_pairs[i0 + 256];
            float f0 = (p0.x < SPLIT) ? sf[p0.x] : __ldg(&frow[p0.x]);
            float f1 = (p1.x < SPLIT) ? sf[p1.x] : __ldg(&frow[p1.x]);
            acc0 = fmaf(f0, __int_as_float(p0.y), acc0);
            acc1 = fmaf(f1, __int_as_float(p1.y), acc1);
        }
        float acc = acc0 + acc1;
        #pragma unroll
        for (int s = 16; s; s >>= 1) acc += __shfl_xor_sync(0xffffffffu, acc, s);
        if (lane == 0)
            s_h[h] = 1.f / (1.f + expf(-(acc + hb[h])));
    }
    __syncthreads();

    // out layer: one warp per output, 8 terms per lane
    if (warp < NOUT) {
        float acc = 0.f;
        #pragma unroll
        for (int i = 0; i < NHID / 32; i++) {
            int j = i * 32 + lane;
            acc = fmaf(s_h[j], ow[warp * NHID + j], acc);
        }
        #pragma unroll
        for (int s = 16; s; s >>= 1) acc += __shfl_xor_sync(0xffffffffu, acc, s);
        if (lane == 0)
            out[b * NOUT + warp] = 1.f / (1.f + expf(-(acc + ob[warp])));
    }
}

// ============================================================
extern "C" void kernel_launch(void* const* d_in, const int* in_sizes, int n_in,
                              void* d_out, int out_size)
{
    const float* inputs = (const float*)d_in[0];
    const float* conv_w = (const float*)d_in[1];
    const float* conv_b = (const float*)d_in[2];
    const int*   hidx   = (const int*)d_in[3];
    const float* hw     = (const float*)d_in[4];
    const float* hb     = (const float*)d_in[5];
    const float* ow     = (const float*)d_in[6];
    const float* ob     = (const float*)d_in[7];

    // idempotent; executes immediately (not a stream op), safe under capture
    cudaFuncSetAttribute(hidden_out_kernel,
                         cudaFuncAttributeMaxDynamicSharedMemorySize, SPLIT * 4);

    conv_pool_kernel<<<dim3(9, BATCH), 224>>>(inputs, conv_w, conv_b, hidx, hw);
    hidden_out_kernel<<<BATCH, 512, SPLIT * 4>>>(hb, ow, ob, (float*)d_out);
}

// round 4
// speedup vs baseline: 4.5315x; 3.0187x over previous
#include <cuda_runtime.h>

// Problem constants
#define BATCH 256
#define HWDIM 128
#define OCN   16
#define PO    63            // pooled spatial dim
#define FTOT  63504         // 16*63*63
#define NHID  256
#define FANIN 512
#define NOUT  10
#define SPLIT 57344         // feats staged in smem for the gather (224 KB)

// Scratch (static device arrays per allocation rules)
__device__ float g_feats[(size_t)BATCH * FTOT];   // pooled features, fp32
__device__ int2  g_pairs[NHID * FANIN];           // packed (idx, w-bits)

// ============================================================
// Kernel A: conv3x3 (VALID) + bias + relu + maxpool2x2 -> g_feats
// R3 rework: one pooled point per thread, tap-major inner loop.
//  - per (c,ky,kx) tap: load w[8] once (2 LDS.128), reuse across the 4 conv
//    sub-pixels of the 2x2 pool window (window held in 16 regs/channel).
//  - two 8-oc passes keep accumulators at 4x8 = 32 regs.
//  - LDS per point: 156 (was 540); FFMA unchanged at 1728.
// Grid: (9 tiles, 256 batches) x 448 threads; launch_bounds(448,2) caps regs
// at 73 -> guaranteed 2 CTAs/SM (28 warps).
// ============================================================
__global__ __launch_bounds__(448, 2) void conv_pool_kernel(
    const float* __restrict__ in,
    const float* __restrict__ cw,
    const float* __restrict__ cb,
    const int*   __restrict__ hidx,
    const float* __restrict__ hw)
{
    __shared__ float s_in[3 * 44 * 44];
    __shared__ float s_w[27][16];      // [tap][oc]; row = 64B, 16B-aligned
    __shared__ float s_b[16];

    const int tile = blockIdx.x;       // 0..8
    const int b    = blockIdx.y;
    const int ty   = tile / 3, tx = tile % 3;
    const int tid  = threadIdx.x;

    // ---- folded pack_pairs: linear CTA id < 512 packs 256 pairs each ----
    {
        const int bid = b * 9 + tile;
        if (bid < 512 && tid < 256) {
            int j = bid * 256 + tid;
            g_pairs[j] = make_int2(hidx[j], __float_as_int(hw[j]));
        }
    }

    // ---- stage weights (transposed) + bias ----
    if (tid < 432) {
        int oc = tid / 27, widx = tid % 27;   // conv_w is [16][27] contiguous
        s_w[widx][oc] = cw[tid];
    }
    if (tid < 16) s_b[tid] = cb[tid];

    // ---- stage input tile 3 x 44 x 44 ----
    const int iy0 = 42 * ty, ix0 = 42 * tx;
    for (int i = tid; i < 3 * 44 * 44; i += 448) {
        int c = i / 1936;
        int r = (i % 1936) / 44;
        int x = i % 44;
        s_in[i] = in[(((size_t)b * 3 + c) * HWDIM + (iy0 + r)) * HWDIM + (ix0 + x)];
    }
    __syncthreads();

    if (tid >= 441) return;
    const int lpy = tid / 21, lpx = tid % 21;
    const int py  = ty * 21 + lpy, px = tx * 21 + lpx;
    float* frow = &g_feats[(size_t)b * FTOT + py * PO + px];

    #pragma unroll
    for (int g = 0; g < 2; g++) {          // 8 output channels per pass
        float acc[4][8];                   // [conv sub-pixel][oc]
        #pragma unroll
        for (int p4 = 0; p4 < 4; p4++)
            #pragma unroll
            for (int o = 0; o < 8; o++) acc[p4][o] = 0.0f;

        #pragma unroll
        for (int c = 0; c < 3; c++) {
            // 4x4 input window for this channel (covers the 2x2 conv pixels)
            float win[4][4];
            #pragma unroll
            for (int yy = 0; yy < 4; yy++) {
                const float* rp = &s_in[c * 1936 + (2 * lpy + yy) * 44 + 2 * lpx];
                float2 v0 = *(const float2*)rp;       // 8B-aligned (2*lpx even)
                float2 v1 = *(const float2*)(rp + 2);
                win[yy][0] = v0.x; win[yy][1] = v0.y;
                win[yy][2] = v1.x; win[yy][3] = v1.y;
            }

            #pragma unroll
            for (int ky = 0; ky < 3; ky++) {
                #pragma unroll
                for (int kx = 0; kx < 3; kx++) {
                    const float4* wp = (const float4*)&s_w[c * 9 + ky * 3 + kx][g * 8];
                    float4 wA = wp[0];                // broadcast LDS.128
                    float4 wB = wp[1];
                    #pragma unroll
                    for (int sy = 0; sy < 2; sy++) {
                        #pragma unroll
                        for (int sx = 0; sx < 2; sx++) {
                            float a = win[ky + sy][kx + sx];
                            float* ac = acc[sy * 2 + sx];
                            ac[0] = fmaf(a, wA.x, ac[0]);
                            ac[1] = fmaf(a, wA.y, ac[1]);
                            ac[2] = fmaf(a, wA.z, ac[2]);
                            ac[3] = fmaf(a, wA.w, ac[3]);
                            ac[4] = fmaf(a, wB.x, ac[4]);
                            ac[5] = fmaf(a, wB.y, ac[5]);
                            ac[6] = fmaf(a, wB.z, ac[6]);
                            ac[7] = fmaf(a, wB.w, ac[7]);
                        }
                    }
                }
            }
        }

        #pragma unroll
        for (int o = 0; o < 8; o++) {
            float m = fmaxf(fmaxf(acc[0][o], acc[1][o]),
                            fmaxf(acc[2][o], acc[3][o]));
            float v = fmaxf(m + s_b[g * 8 + o], 0.0f);  // max(relu)==relu(max)+b
            frow[(size_t)(g * 8 + o) * (PO * PO)] = v;
        }
    }
}

// ============================================================
// Kernel B (fused): hidden = sigmoid(gather-dot + hb), then
// out = sigmoid(hidden @ out_w^T + ob). One CTA per batch, 1024 threads.
// First SPLIT feats staged in 224 KB smem; ~90% of gathers become LDS,
// tail (6160 feats = 24.6 KB) stays L2-resident via __ldg.
// ============================================================
__global__ __launch_bounds__(1024) void hidden_out_kernel(
    const float* __restrict__ hb,
    const float* __restrict__ ow,
    const float* __restrict__ ob,
    float* __restrict__ out)
{
    extern __shared__ float sf[];      // SPLIT floats
    __shared__ float s_h[NHID];

    const int b = blockIdx.x;
    const float* frow = g_feats + (size_t)b * FTOT;

    // stage fp32 feats (vectorized; SPLIT divisible by 4)
    {
        const float4* s4 = (const float4*)frow;
        float4* d4 = (float4*)sf;
        for (int i = threadIdx.x; i < SPLIT / 4; i += 1024) d4[i] = s4[i];
    }
    __syncthreads();

    const int warp = threadIdx.x >> 5, lane = threadIdx.x & 31;

    for (int h = warp; h < NHID; h += 32) {
        float acc0 = 0.f, acc1 = 0.f;
        #pragma unroll
        for (int it = 0; it < 8; it++) {
            int  i0 = h * FANIN + it * 32 + lane;
            int2 p0 = g_pairs[i0];
            int2 p1 = g_pairs[i0 + 256];
            float f0 = (p0.x < SPLIT) ? sf[p0.x] : __ldg(&frow[p0.x]);
            float f1 = (p1.x < SPLIT) ? sf[p1.x] : __ldg(&frow[p1.x]);
            acc0 = fmaf(f0, __int_as_float(p0.y), acc0);
            acc1 = fmaf(f1, __int_as_float(p1.y), acc1);
        }
        float acc = acc0 + acc1;
        #pragma unroll
        for (int s = 16; s; s >>= 1) acc += __shfl_xor_sync(0xffffffffu, acc, s);
        if (lane == 0)
            s_h[h] = 1.f / (1.f + expf(-(acc + hb[h])));
    }
    __syncthreads();

    // out layer: one warp per output, 8 terms per lane
    if (warp < NOUT) {
        float acc = 0.f;
        #pragma unroll
        for (int i = 0; i < NHID / 32; i++) {
            int j = i * 32 + lane;
            acc = fmaf(s_h[j], ow[warp * NHID + j], acc);
        }
        #pragma unroll
        for (int s = 16; s; s >>= 1) acc += __shfl_xor_sync(0xffffffffu, acc, s);
        if (lane == 0)
            out[b * NOUT + warp] = 1.f / (1.f + expf(-(acc + ob[warp])));
    }
}

// ============================================================
extern "C" void kernel_launch(void* const* d_in, const int* in_sizes, int n_in,
                              void* d_out, int out_size)
{
    const float* inputs = (const float*)d_in[0];
    const float* conv_w = (const float*)d_in[1];
    const float* conv_b = (const float*)d_in[2];
    const int*   hidx   = (const int*)d_in[3];
    const float* hw     = (const float*)d_in[4];
    const float* hb     = (const float*)d_in[5];
    const float* ow     = (const float*)d_in[6];
    const float* ob     = (const float*)d_in[7];

    // idempotent; executes immediately (not a stream op), safe under capture
    cudaFuncSetAttribute(hidden_out_kernel,
                         cudaFuncAttributeMaxDynamicSharedMemorySize, SPLIT * 4);

    conv_pool_kernel<<<dim3(9, BATCH), 448>>>(inputs, conv_w, conv_b, hidx, hw);
    hidden_out_kernel<<<BATCH, 1024, SPLIT * 4>>>(hb, ow, ob, (float*)d_out);
}

// round 5
// speedup vs baseline: 4.6708x; 1.0308x over previous
#include <cuda_runtime.h>

// Problem constants
#define BATCH 256
#define HWDIM 128
#define OCN   16
#define PO    63            // pooled spatial dim
#define FTOT  63504         // 16*63*63
#define NHID  256
#define FANIN 512
#define NOUT  10

// Scratch (static device arrays per allocation rules)
__device__ float g_feats[(size_t)BATCH * FTOT];    // pooled feats, [b][f]
__device__ float g_feats_T[(size_t)FTOT * BATCH];  // transposed,   [f][b]
__device__ float g_hidden_T[NHID * BATCH];         // hidden,       [h][b]

// ============================================================
// Kernel A: conv3x3 (VALID) + bias + relu + maxpool2x2 -> g_feats[b][f]
// One pooled point per thread, tap-major inner loop (R4 structure, validated
// at ~134us). Grid: (9 tiles, 256 batches) x 448 thr, launch_bounds(448,2).
// ============================================================
__global__ __launch_bounds__(448, 2) void conv_pool_kernel(
    const float* __restrict__ in,
    const float* __restrict__ cw,
    const float* __restrict__ cb)
{
    __shared__ float s_in[3 * 44 * 44];
    __shared__ float s_w[27][16];      // [tap][oc]; row = 64B, 16B-aligned
    __shared__ float s_b[16];

    const int tile = blockIdx.x;       // 0..8
    const int b    = blockIdx.y;
    const int ty   = tile / 3, tx = tile % 3;
    const int tid  = threadIdx.x;

    if (tid < 432) {
        int oc = tid / 27, widx = tid % 27;   // conv_w is [16][27] contiguous
        s_w[widx][oc] = cw[tid];
    }
    if (tid < 16) s_b[tid] = cb[tid];

    const int iy0 = 42 * ty, ix0 = 42 * tx;
    for (int i = tid; i < 3 * 44 * 44; i += 448) {
        int c = i / 1936;
        int r = (i % 1936) / 44;
        int x = i % 44;
        s_in[i] = in[(((size_t)b * 3 + c) * HWDIM + (iy0 + r)) * HWDIM + (ix0 + x)];
    }
    __syncthreads();

    if (tid >= 441) return;
    const int lpy = tid / 21, lpx = tid % 21;
    const int py  = ty * 21 + lpy, px = tx * 21 + lpx;
    float* frow = &g_feats[(size_t)b * FTOT + py * PO + px];

    #pragma unroll
    for (int g = 0; g < 2; g++) {          // 8 output channels per pass
        float acc[4][8];                   // [conv sub-pixel][oc]
        #pragma unroll
        for (int p4 = 0; p4 < 4; p4++)
            #pragma unroll
            for (int o = 0; o < 8; o++) acc[p4][o] = 0.0f;

        #pragma unroll
        for (int c = 0; c < 3; c++) {
            float win[4][4];
            #pragma unroll
            for (int yy = 0; yy < 4; yy++) {
                const float* rp = &s_in[c * 1936 + (2 * lpy + yy) * 44 + 2 * lpx];
                float2 v0 = *(const float2*)rp;       // 8B-aligned (2*lpx even)
                float2 v1 = *(const float2*)(rp + 2);
                win[yy][0] = v0.x; win[yy][1] = v0.y;
                win[yy][2] = v1.x; win[yy][3] = v1.y;
            }

            #pragma unroll
            for (int ky = 0; ky < 3; ky++) {
                #pragma unroll
                for (int kx = 0; kx < 3; kx++) {
                    const float4* wp = (const float4*)&s_w[c * 9 + ky * 3 + kx][g * 8];
                    float4 wA = wp[0];                // broadcast LDS.128
                    float4 wB = wp[1];
                    #pragma unroll
                    for (int sy = 0; sy < 2; sy++) {
                        #pragma unroll
                        for (int sx = 0; sx < 2; sx++) {
                            float a = win[ky + sy][kx + sx];
                            float* ac = acc[sy * 2 + sx];
                            ac[0] = fmaf(a, wA.x, ac[0]);
                            ac[1] = fmaf(a, wA.y, ac[1]);
                            ac[2] = fmaf(a, wA.z, ac[2]);
                            ac[3] = fmaf(a, wA.w, ac[3]);
                            ac[4] = fmaf(a, wB.x, ac[4]);
                            ac[5] = fmaf(a, wB.y, ac[5]);
                            ac[6] = fmaf(a, wB.z, ac[6]);
                            ac[7] = fmaf(a, wB.w, ac[7]);
                        }
                    }
                }
            }
        }

        #pragma unroll
        for (int o = 0; o < 8; o++) {
            float m = fmaxf(fmaxf(acc[0][o], acc[1][o]),
                            fmaxf(acc[2][o], acc[3][o]));
            float v = fmaxf(m + s_b[g * 8 + o], 0.0f);  // max(relu)==relu(max)+b
            frow[(size_t)(g * 8 + o) * (PO * PO)] = v;
        }
    }
}

// ============================================================
// Kernel T: transpose g_feats[b][f] -> g_feats_T[f][b], 32x32 smem tiles.
// Both sides fully coalesced; ~130MB of (mostly L2-resident) traffic.
// ============================================================
__global__ __launch_bounds__(256) void transpose_kernel()
{
    __shared__ float t[32][33];
    const int f0 = blockIdx.x * 32, b0 = blockIdx.y * 32;
    const int tx = threadIdx.x & 31, ty = threadIdx.x >> 5;   // 32 x 8

    #pragma unroll
    for (int j = 0; j < 4; j++) {
        int f = f0 + tx;
        int b = b0 + ty + 8 * j;
        t[ty + 8 * j][tx] = (f < FTOT) ? g_feats[(size_t)b * FTOT + f] : 0.0f;
    }
    __syncthreads();
    #pragma unroll
    for (int j = 0; j < 4; j++) {
        int f = f0 + ty + 8 * j;
        int b = b0 + tx;
        if (f < FTOT) g_feats_T[(size_t)f * BATCH + b] = t[tx][ty + 8 * j];
    }
}

// ============================================================
// Kernel B: hidden_T[h][b] = sigmoid(sum_k feats_T[idx[h,k]][b]*w[h,k]+hb[h])
// One CTA per h, 512 threads = (k-half, batch). Pairs staged once per h
// (1MB total chip-wide, was 256MB); every feat load is a coalesced 128B
// warp access to L2-resident feats_T.
// ============================================================
__global__ __launch_bounds__(512) void gather_hidden_kernel(
    const int*   __restrict__ hidx,
    const float* __restrict__ hw,
    const float* __restrict__ hb)
{
    __shared__ int   s_idx[FANIN];
    __shared__ float s_w[FANIN];
    __shared__ float s_part[BATCH];

    const int h   = blockIdx.x;
    const int tid = threadIdx.x;

    s_idx[tid] = hidx[h * FANIN + tid];
    s_w[tid]   = hw[h * FANIN + tid];
    __syncthreads();

    const int b    = tid & 255;
    const int half = tid >> 8;         // 0/1
    const int k0   = half * 256;

    float acc = 0.0f;
    #pragma unroll 8
    for (int k = 0; k < 256; k++) {
        int idx = s_idx[k0 + k];       // broadcast LDS
        acc = fmaf(g_feats_T[(size_t)idx * BATCH + b], s_w[k0 + k], acc);
    }

    if (half) s_part[b] = acc;
    __syncthreads();
    if (!half) {
        float tot = acc + s_part[b];
        g_hidden_T[h * BATCH + b] = 1.0f / (1.0f + expf(-(tot + hb[h])));
    }
}

// ============================================================
// Kernel C: out[b][o] = sigmoid(sum_h hidden_T[h][b]*ow[o][h] + ob[o])
// One CTA per output o, thread = batch; hidden_T reads coalesced.
// ============================================================
__global__ __launch_bounds__(256) void out_kernel(
    const float* __restrict__ ow,
    const float* __restrict__ ob,
    float* __restrict__ out)
{
    __shared__ float s_w[NHID];
    const int o = blockIdx.x, tid = threadIdx.x;

    s_w[tid] = ow[o * NHID + tid];
    __syncthreads();

    float acc = 0.0f;
    #pragma unroll 8
    for (int h = 0; h < NHID; h++)
        acc = fmaf(g_hidden_T[h * BATCH + tid], s_w[h], acc);

    out[tid * NOUT + o] = 1.0f / (1.0f + expf(-(acc + ob[o])));
}

// ============================================================
extern "C" void kernel_launch(void* const* d_in, const int* in_sizes, int n_in,
                              void* d_out, int out_size)
{
    const float* inputs = (const float*)d_in[0];
    const float* conv_w = (const float*)d_in[1];
    const float* conv_b = (const float*)d_in[2];
    const int*   hidx   = (const int*)d_in[3];
    const float* hw     = (const float*)d_in[4];
    const float* hb     = (const float*)d_in[5];
    const float* ow     = (const float*)d_in[6];
    const float* ob     = (const float*)d_in[7];

    conv_pool_kernel<<<dim3(9, BATCH), 448>>>(inputs, conv_w, conv_b);
    transpose_kernel<<<dim3((FTOT + 31) / 32, BATCH / 32), 256>>>();
    gather_hidden_kernel<<<NHID, 512>>>(hidx, hw, hb);
    out_kernel<<<NOUT, 256>>>(ow, ob, (float*)d_out);
}